// round 13
// baseline (speedup 1.0000x reference)
#include <cuda_runtime.h>
#include <cstdint>

// Problem constants
#define N_ENT   500000
#define B_SZ    16384
#define NNEG    10
#define D_DIM   8
#define E_DIM   64
#define NSCORES (B_SZ * (1 + NNEG))   // 180224

// int8 scale: values ~N(0,0.01); S=2048 -> |q|max ~113 < 127.
// acc = Sum_{i<j} dot(q_i,q_j) exactly in int32; pair-sum = acc / S^2.
#define QSCALE  2048.0f
#define INV_S2  (1.0f / (2048.0f * 2048.0f))

#define TAB_WORDS   (N_ENT * E_DIM / 4)     // 8,000,000 uint32 = 32 MB
#define WARM_BLOCKS 256                     // L2 re-warm blocks (prefetch sweep)
#define SCORE_BLOCKS ((NSCORES / 2 + 31) / 32)   // 2816 (32 groups per block)

// Static scratch: int8 table (32 MB).
__device__ __align__(16) unsigned int g_emb8[TAB_WORDS];

// ---- policy helpers (conv unchanged from R12) ----
__device__ __forceinline__ uint64_t policy_evict_last() {
    uint64_t pol;
    asm("createpolicy.fractional.L2::evict_last.b64 %0, 1.0;" : "=l"(pol));
    return pol;
}
__device__ __forceinline__ uint64_t policy_evict_first() {
    uint64_t pol;
    asm("createpolicy.fractional.L2::evict_first.b64 %0, 1.0;" : "=l"(pol));
    return pol;
}
__device__ __forceinline__ float4 ldg_stream_f4(const float4* p, uint64_t pol) {
    float4 v;
    asm("ld.global.nc.L2::cache_hint.v4.f32 {%0,%1,%2,%3}, [%4], %5;"
        : "=f"(v.x), "=f"(v.y), "=f"(v.z), "=f"(v.w) : "l"(p), "l"(pol));
    return v;
}
__device__ __forceinline__ void stg_sticky_u4(unsigned int* p, uint4 o, uint64_t pol) {
    asm volatile("st.global.L2::cache_hint.v4.b32 [%0], {%1,%2,%3,%4}, %5;"
                 :: "l"(p), "r"(o.x), "r"(o.y), "r"(o.z), "r"(o.w), "l"(pol)
                 : "memory");
}

__device__ __forceinline__ unsigned int pack4_s8(float a, float b, float c, float d) {
    int q0 = max(-127, min(127, __float2int_rn(a)));
    int q1 = max(-127, min(127, __float2int_rn(b)));
    int q2 = max(-127, min(127, __float2int_rn(c)));
    int q3 = max(-127, min(127, __float2int_rn(d)));
    return (q0 & 0xFF) | ((q1 & 0xFF) << 8) | ((q2 & 0xFF) << 16)
         | ((unsigned int)(q3 & 0xFF) << 24);
}

// Kernel 1: fp32 -> int8 (x2048). Unchanged from R12 (19.8us known).
__global__ __launch_bounds__(256) void APE_convert_kernel(
    const float* __restrict__ emb)
{
    const int t = blockIdx.x * blockDim.x + threadIdx.x;   // 2M threads
    if (t >= N_ENT * E_DIM / 16) return;
    const float4* src = reinterpret_cast<const float4*>(emb) + t * 4;

    const uint64_t pf = policy_evict_first();
    float4 v0 = ldg_stream_f4(src + 0, pf);
    float4 v1 = ldg_stream_f4(src + 1, pf);
    float4 v2 = ldg_stream_f4(src + 2, pf);
    float4 v3 = ldg_stream_f4(src + 3, pf);

    uint4 o;
    o.x = pack4_s8(v0.x*QSCALE, v0.y*QSCALE, v0.z*QSCALE, v0.w*QSCALE);
    o.y = pack4_s8(v1.x*QSCALE, v1.y*QSCALE, v1.z*QSCALE, v1.w*QSCALE);
    o.z = pack4_s8(v2.x*QSCALE, v2.y*QSCALE, v2.z*QSCALE, v2.w*QSCALE);
    o.w = pack4_s8(v3.x*QSCALE, v3.y*QSCALE, v3.z*QSCALE, v3.w*QSCALE);

    const uint64_t pl = policy_evict_last();
    stg_sticky_u4(g_emb8 + t * 4, o, pl);
}

// Kernel 2: blocks [0, WARM_BLOCKS) re-warm the int8 table into L2 via a
// sequential prefetch sweep (turns ~30MB of random 64B cold misses into a
// ~5us streaming burst). Blocks [WARM_BLOCKS, ...) score: two scores per
// 8-lane group, 16 batched gathers, 56 dp4a per score (exact int32).
__global__ __launch_bounds__(256) void APE_61555471286335_kernel(
    const int*   __restrict__ pos_x,    // [B, D]
    const int*   __restrict__ neg_x,    // [B, NNEG, D]
    const float* __restrict__ pair_w,   // [28]
    const float* __restrict__ cc,       // [1]
    float*       __restrict__ out)      // [NSCORES] = pos(B) ++ neg(B*NNEG)
{
    if (blockIdx.x < WARM_BLOCKS) {
        // ---- L2 warmer: prefetch all 262144 lines of g_emb8 ----
        const int t = blockIdx.x * 256 + threadIdx.x;   // 65536 threads
        const char* base = reinterpret_cast<const char*>(g_emb8);
        #pragma unroll
        for (int i = 0; i < 4; i++) {
            const char* p = base + ((size_t)(t + i * (WARM_BLOCKS * 256)) << 7);
            asm volatile("prefetch.global.L2 [%0];" :: "l"(p));
        }
        return;
    }

    const int grp  = (blockIdx.x - WARM_BLOCKS) * 32 + (threadIdx.x >> 3);
    const int lane = threadIdx.x & 7;
    if (grp >= NSCORES / 2) return;
    const int g0 = grp * 2;
    const int g1 = g0 + 1;

    const int4* ip0 = (g0 < B_SZ)
        ? reinterpret_cast<const int4*>(pos_x + g0 * D_DIM)
        : reinterpret_cast<const int4*>(neg_x + (g0 - B_SZ) * D_DIM);
    const int4* ip1 = (g1 < B_SZ)
        ? reinterpret_cast<const int4*>(pos_x + g1 * D_DIM)
        : reinterpret_cast<const int4*>(neg_x + (g1 - B_SZ) * D_DIM);
    const int4 a0 = __ldg(ip0);
    const int4 a1 = __ldg(ip0 + 1);
    const int4 b0 = __ldg(ip1);
    const int4 b1 = __ldg(ip1 + 1);

    unsigned int rows[16] = {
        (unsigned)a0.x, (unsigned)a0.y, (unsigned)a0.z, (unsigned)a0.w,
        (unsigned)a1.x, (unsigned)a1.y, (unsigned)a1.z, (unsigned)a1.w,
        (unsigned)b0.x, (unsigned)b0.y, (unsigned)b0.z, (unsigned)b0.w,
        (unsigned)b1.x, (unsigned)b1.y, (unsigned)b1.z, (unsigned)b1.w
    };

    const uint2* tab = reinterpret_cast<const uint2*>(g_emb8) + lane;
    uint2 w[16];
    #pragma unroll
    for (int k = 0; k < 16; k++)
        w[k] = __ldg(tab + rows[k] * (E_DIM / 8));

    int acc0a = 0, acc0b = 0, acc1a = 0, acc1b = 0;
    #pragma unroll
    for (int i = 0; i < D_DIM; i++) {
        #pragma unroll
        for (int j = i + 1; j < D_DIM; j++) {
            acc0a = __dp4a((int)w[i].x,     (int)w[j].x,     acc0a);
            acc0b = __dp4a((int)w[i].y,     (int)w[j].y,     acc0b);
            acc1a = __dp4a((int)w[8 + i].x, (int)w[8 + j].x, acc1a);
            acc1b = __dp4a((int)w[8 + i].y, (int)w[8 + j].y, acc1b);
        }
    }
    int acc0 = acc0a + acc0b;
    int acc1 = acc1a + acc1b;

    #pragma unroll
    for (int off = 4; off > 0; off >>= 1) {
        acc0 += __shfl_down_sync(0xFFFFFFFFu, acc0, off, 8);
        acc1 += __shfl_down_sync(0xFFFFFFFFu, acc1, off, 8);
    }

    if (lane == 0) {
        const float wgt = expf(__ldg(pair_w)) * INV_S2;   // exp(pair_w[0])/S^2
        const float c0  = __ldg(cc);
        out[g0] = expf((float)acc0 * wgt + c0);
        out[g1] = expf((float)acc1 * wgt + c0);
    }
}

extern "C" void kernel_launch(void* const* d_in, const int* in_sizes, int n_in,
                              void* d_out, int out_size)
{
    const int*   pos_x  = (const int*)  d_in[0];
    const int*   neg_x  = (const int*)  d_in[1];
    const float* emb    = (const float*)d_in[2];
    const float* pair_w = (const float*)d_in[3];
    const float* cc     = (const float*)d_in[4];
    float*       out    = (float*)d_out;

    // 1) fp32 -> int8 table
    {
        const int n     = N_ENT * E_DIM / 16;            // 2,000,000
        const int block = 256;
        const int grid  = (n + block - 1) / block;       // 7813
        APE_convert_kernel<<<grid, block>>>(emb);
    }
    // 2) warm + scores (warm blocks first in the grid -> wave 1)
    APE_61555471286335_kernel<<<WARM_BLOCKS + SCORE_BLOCKS, 256>>>(
        pos_x, neg_x, pair_w, cc, out);
}

// round 14
// speedup vs baseline: 1.0697x; 1.0697x over previous
#include <cuda_runtime.h>

// Problem constants (match reference)
#define B_SZ    16384
#define NNEG    10
#define D_DIM   8
#define E_DIM   64
#define NSCORES (B_SZ * (1 + NNEG))   // 180224

// One score per 16-lane half-warp; each lane owns one float4 (16B) of E=64.
// score(g) = exp( 0.5*(|sum_d e_d|^2 - sum_d |e_d|^2) * exp(pw0) + c )
//
// Session conclusion: this single-pass fp32 form sits simultaneously at the
// LTS byte cap (369 MB @ ~11.1 TB/s) and the DRAM random-gather limit
// (~180 MB @ ~5.2 TB/s). All compression (fp8/int8 two-pass), overlap,
// cache-policy, and prefetch variants measured >= 35 us; this is the fastest
// verified configuration.
__global__ __launch_bounds__(256) void APE_61555471286335_kernel(
    const int*   __restrict__ pos_x,    // [B, D]
    const int*   __restrict__ neg_x,    // [B, NNEG, D]
    const float* __restrict__ emb,      // [N_ENT, E]
    const float* __restrict__ pair_w,   // [28]
    const float* __restrict__ cc,       // [1]
    float*       __restrict__ out)      // [NSCORES] = pos(B) ++ neg(B*NNEG)
{
    const int tid  = blockIdx.x * blockDim.x + threadIdx.x;
    const int g    = tid >> 4;            // score index
    if (g >= NSCORES) return;
    const int lane = threadIdx.x & 15;    // lane within half-warp (0..15)

    // Gather the 8 row indices: lanes 0..7 load, then shfl-broadcast (hoisted).
    const int* idx = (g < B_SZ) ? (pos_x + g * D_DIM)
                                : (neg_x + (g - B_SZ) * D_DIM);
    int myidx = 0;
    if (lane < D_DIM) myidx = __ldg(idx + lane);

    int rows[D_DIM];
    #pragma unroll
    for (int d = 0; d < D_DIM; d++)
        rows[d] = __shfl_sync(0xFFFFFFFFu, myidx, d, 16);

    // Issue all 8 gathers back-to-back: independent LDG.128, MLP=8.
    // 16 lanes x 16B = 256B fully coalesced row (2 lines).
    float4 v[D_DIM];
    #pragma unroll
    for (int d = 0; d < D_DIM; d++) {
        const float4* e = reinterpret_cast<const float4*>(
            emb + (size_t)rows[d] * E_DIM);
        v[d] = __ldg(e + lane);
    }

    // Accumulate after all loads are in flight.
    float4 s = make_float4(0.f, 0.f, 0.f, 0.f);
    float sumsq = 0.f;
    #pragma unroll
    for (int d = 0; d < D_DIM; d++) {
        s.x += v[d].x; s.y += v[d].y; s.z += v[d].z; s.w += v[d].w;
        sumsq = fmaf(v[d].x, v[d].x, sumsq);
        sumsq = fmaf(v[d].y, v[d].y, sumsq);
        sumsq = fmaf(v[d].z, v[d].z, sumsq);
        sumsq = fmaf(v[d].w, v[d].w, sumsq);
    }

    // per-lane: |s_lane|^2 - sumsq_lane ; then 16-lane tree reduce
    float val = s.x * s.x + s.y * s.y + s.z * s.z + s.w * s.w - sumsq;
    #pragma unroll
    for (int off = 8; off > 0; off >>= 1)
        val += __shfl_down_sync(0xFFFFFFFFu, val, off, 16);

    if (lane == 0) {
        const float w = expf(__ldg(pair_w));   // exp(pair_w[0])
        out[g] = expf(0.5f * val * w + __ldg(cc));
    }
}

extern "C" void kernel_launch(void* const* d_in, const int* in_sizes, int n_in,
                              void* d_out, int out_size)
{
    const int*   pos_x  = (const int*)  d_in[0];
    const int*   neg_x  = (const int*)  d_in[1];
    const float* emb    = (const float*)d_in[2];
    const float* pair_w = (const float*)d_in[3];
    const float* cc     = (const float*)d_in[4];
    float*       out    = (float*)d_out;

    const int total_threads = NSCORES * 16;           // 2,883,584
    const int block = 256;
    const int grid  = (total_threads + block - 1) / block;  // 11264
    APE_61555471286335_kernel<<<grid, block>>>(pos_x, neg_x, emb, pair_w, cc, out);
}